// round 1
// baseline (speedup 1.0000x reference)
#include <cuda_runtime.h>
#include <cuda_bf16.h>
#include <cstdint>

// QuantizedLinearLayer: out[T,N] = (x[T,K] @ W[N,K]^T) * scales[N] + bias[N]
// T=8192, K=4096, N=4096. x fp32, W int8-valued int32, out fp32.
//
// R0 baseline: SIMT tiled GEMM, 128x128 block tile, BK=16, 8x8 per thread,
// fp32 accumulation via packed fma.rn.f32x2 (2 FMAs/instr; 3-reg scalar FFMA
// is half-rate on sm_103a per measured rt tables).

#define BM 128
#define BN 128
#define BK 16
#define TM 8
#define TN 8

__global__ __launch_bounds__(256, 2)
void qlinear_f32x2_kernel(const float* __restrict__ X,
                          const int*   __restrict__ W,
                          const float* __restrict__ scales,
                          const float* __restrict__ bias,
                          float* __restrict__ Out,
                          int T, int N, int K)
{
    // A tile stored k-major-of-m: As[k][m]; pad to reduce STS conflicts.
    __shared__ __align__(16) float As[BK][BM + 1];
    // B tile As[k][n]; pad by 2 floats to keep 8B alignment for u64 reads.
    __shared__ __align__(16) float Bs[BK][BN + 2];

    const int tid = threadIdx.x;
    const int bx = blockIdx.x;   // n tile
    const int by = blockIdx.y;   // m tile

    const int tx = tid & 15;     // 16 threads across N
    const int ty = tid >> 4;     // 16 threads across M

    const float* Ablk = X + (size_t)by * BM * K;
    const int*   Bblk = W + (size_t)bx * BN * K;

    // accumulators: 8 rows x 4 f32x2 pairs (8 cols), packed in u64
    unsigned long long acc[TM][TN / 2];
    #pragma unroll
    for (int i = 0; i < TM; i++)
        #pragma unroll
        for (int j = 0; j < TN / 2; j++)
            acc[i][j] = 0ULL;   // {0.0f, 0.0f}

    for (int kk = 0; kk < K; kk += BK) {
        // ---- global -> shared: A (fp32, transposed store) ----
        #pragma unroll
        for (int it = 0; it < 2; it++) {
            int idx = tid + it * 256;     // 512 float4 total
            int row = idx >> 2;           // 0..127 (m)
            int c4  = idx & 3;            // which float4 in the 16-wide k slab
            float4 v = *reinterpret_cast<const float4*>(
                Ablk + (size_t)row * K + kk + c4 * 4);
            As[c4 * 4 + 0][row] = v.x;
            As[c4 * 4 + 1][row] = v.y;
            As[c4 * 4 + 2][row] = v.z;
            As[c4 * 4 + 3][row] = v.w;
        }
        // ---- global -> shared: W (int32 -> fp32, exact for int8 range) ----
        #pragma unroll
        for (int it = 0; it < 2; it++) {
            int idx = tid + it * 256;
            int row = idx >> 2;           // 0..127 (n)
            int c4  = idx & 3;
            int4 v = *reinterpret_cast<const int4*>(
                Bblk + (size_t)row * K + kk + c4 * 4);
            Bs[c4 * 4 + 0][row] = (float)v.x;
            Bs[c4 * 4 + 1][row] = (float)v.y;
            Bs[c4 * 4 + 2][row] = (float)v.z;
            Bs[c4 * 4 + 3][row] = (float)v.w;
        }
        __syncthreads();

        #pragma unroll
        for (int k = 0; k < BK; k++) {
            // B: 4 packed pairs = 8 consecutive n-columns
            unsigned long long bp[TN / 2];
            const unsigned long long* brow =
                reinterpret_cast<const unsigned long long*>(&Bs[k][tx * TN]);
            #pragma unroll
            for (int j = 0; j < TN / 2; j++) bp[j] = brow[j];

            #pragma unroll
            for (int i = 0; i < TM; i++) {
                float a = As[k][ty * TM + i];
                unsigned long long ap;
                asm("mov.b64 %0, {%1, %1};"
                    : "=l"(ap) : "r"(__float_as_uint(a)));
                #pragma unroll
                for (int j = 0; j < TN / 2; j++) {
                    asm("fma.rn.f32x2 %0, %1, %2, %0;"
                        : "+l"(acc[i][j]) : "l"(ap), "l"(bp[j]));
                }
            }
        }
        __syncthreads();
    }

    // ---- epilogue: scale + bias, vectorized store ----
    const int m0 = by * BM + ty * TM;
    const int n0 = bx * BN + tx * TN;

    float4 s0 = *reinterpret_cast<const float4*>(scales + n0);
    float4 s1 = *reinterpret_cast<const float4*>(scales + n0 + 4);
    float4 b0 = *reinterpret_cast<const float4*>(bias + n0);
    float4 b1 = *reinterpret_cast<const float4*>(bias + n0 + 4);

    #pragma unroll
    for (int i = 0; i < TM; i++) {
        float c[TN];
        #pragma unroll
        for (int j = 0; j < TN / 2; j++) {
            unsigned int lo = (unsigned int)(acc[i][j] & 0xffffffffULL);
            unsigned int hi = (unsigned int)(acc[i][j] >> 32);
            c[2 * j + 0] = __uint_as_float(lo);
            c[2 * j + 1] = __uint_as_float(hi);
        }
        float4 o0, o1;
        o0.x = c[0] * s0.x + b0.x;
        o0.y = c[1] * s0.y + b0.y;
        o0.z = c[2] * s0.z + b0.z;
        o0.w = c[3] * s0.w + b0.w;
        o1.x = c[4] * s1.x + b1.x;
        o1.y = c[5] * s1.y + b1.y;
        o1.z = c[6] * s1.z + b1.z;
        o1.w = c[7] * s1.w + b1.w;
        float* orow = Out + (size_t)(m0 + i) * N + n0;
        *reinterpret_cast<float4*>(orow)     = o0;
        *reinterpret_cast<float4*>(orow + 4) = o1;
    }
}

extern "C" void kernel_launch(void* const* d_in, const int* in_sizes, int n_in,
                              void* d_out, int out_size)
{
    const float* x      = (const float*)d_in[0];
    const int*   w      = (const int*)d_in[1];
    const float* scales = (const float*)d_in[2];
    const float* bias   = (const float*)d_in[3];
    float* out = (float*)d_out;

    const int N = in_sizes[2];                 // d_out dim = 4096
    const int K = in_sizes[1] / N;             // 4096
    const int T = in_sizes[0] / K;             // 8192

    dim3 grid(N / BN, T / BM);
    qlinear_f32x2_kernel<<<grid, 256>>>(x, w, scales, bias, out, T, N, K);
}

// round 3
// speedup vs baseline: 2.8997x; 2.8997x over previous
#include <cuda_runtime.h>
#include <cuda_bf16.h>
#include <mma.h>
#include <cstdint>

// QuantizedLinearLayer: out[T,N] = (x[T,K] @ W[N,K]^T) * scales[N] + bias[N]
// T=8192, K=4096, N=4096.
//
// R2: x split into hi/lo bf16 digits (fp32-accurate to ~2^-17); W exact in
// bf16. One GEMM kernel symbol, two bodies:
//   - sm_103a pass (__CUDA_ARCH_FEAT_SM103_ALL): tcgen05 SS-mode UTCHMMA,
//     128x256 CTA tile, TMEM accumulator, double-buffered smem.
//   - plain sm_103 pass: wmma bf16 16x16x16 (HMMA), same tile/launch config.
// The fatbin loader picks the best-matching SASS at runtime.

#define T_DIM 8192
#define N_DIM 4096
#define K_DIM 4096

#define BM 128
#define BN 256
#define BK 64
#define NCHUNK (K_DIM / BK)   // 64
#define THREADS 256

// ---- scratch (static device arrays are the allowed scratch path) ----
__device__ __nv_bfloat16 g_xh[(size_t)T_DIM * K_DIM];
__device__ __nv_bfloat16 g_xl[(size_t)T_DIM * K_DIM];
__device__ __nv_bfloat16 g_wb[(size_t)N_DIM * K_DIM];

// ---- SMEM layout (bytes from dynamic smem base) ----
#define OFF_TMEMPTR 0
#define OFF_MBAR    8
#define OFF_BUF     1024
#define AH_OFF      0
#define AL_OFF      16384
#define BB_OFF      32768
#define STAGE_BYTES 65536
#define SMEM_TOTAL  (OFF_BUF + 2 * STAGE_BYTES)   // 132096

// idesc: f32 accum, bf16 A/B, K-major, M=128, N=256
#define MMA_IDESC ((1u << 4) | (1u << 7) | (1u << 10) | ((BN / 8) << 17) | ((BM / 16) << 24))

__device__ __forceinline__ uint32_t smem_u32(const void* p) {
    uint32_t a;
    asm("{ .reg .u64 t; cvta.to.shared.u64 t, %1; cvt.u32.u64 %0, t; }" : "=r"(a) : "l"(p));
    return a;
}

// ---------------- prepass kernels (arch-neutral) ----------------
__global__ void convert_x_kernel(const float4* __restrict__ X4, int n4) {
    int i = blockIdx.x * blockDim.x + threadIdx.x;
    if (i >= n4) return;
    float4 v = X4[i];
    __nv_bfloat16 h0 = __float2bfloat16(v.x);
    __nv_bfloat16 h1 = __float2bfloat16(v.y);
    __nv_bfloat16 h2 = __float2bfloat16(v.z);
    __nv_bfloat16 h3 = __float2bfloat16(v.w);
    __nv_bfloat16 l0 = __float2bfloat16(v.x - __bfloat162float(h0));
    __nv_bfloat16 l1 = __float2bfloat16(v.y - __bfloat162float(h1));
    __nv_bfloat16 l2 = __float2bfloat16(v.z - __bfloat162float(h2));
    __nv_bfloat16 l3 = __float2bfloat16(v.w - __bfloat162float(h3));
    ushort4 hv, lv;
    hv.x = __bfloat16_as_ushort(h0); hv.y = __bfloat16_as_ushort(h1);
    hv.z = __bfloat16_as_ushort(h2); hv.w = __bfloat16_as_ushort(h3);
    lv.x = __bfloat16_as_ushort(l0); lv.y = __bfloat16_as_ushort(l1);
    lv.z = __bfloat16_as_ushort(l2); lv.w = __bfloat16_as_ushort(l3);
    *reinterpret_cast<ushort4*>(g_xh + (size_t)i * 4) = hv;
    *reinterpret_cast<ushort4*>(g_xl + (size_t)i * 4) = lv;
}

__global__ void convert_w_kernel(const int4* __restrict__ W4, int n4) {
    int i = blockIdx.x * blockDim.x + threadIdx.x;
    if (i >= n4) return;
    int4 v = W4[i];
    ushort4 wv;
    wv.x = __bfloat16_as_ushort(__float2bfloat16((float)v.x));
    wv.y = __bfloat16_as_ushort(__float2bfloat16((float)v.y));
    wv.z = __bfloat16_as_ushort(__float2bfloat16((float)v.z));
    wv.w = __bfloat16_as_ushort(__float2bfloat16((float)v.w));
    *reinterpret_cast<ushort4*>(g_wb + (size_t)i * 4) = wv;
}

#if defined(__CUDA_ARCH_FEAT_SM103_ALL)
// ================= tcgen05 path (sm_103a device pass) =================

__device__ __forceinline__ uint32_t elect_one() {
    uint32_t p;
    asm volatile("{ .reg .pred p; elect.sync _|p, 0xFFFFFFFF; selp.b32 %0, 1, 0, p; }" : "=r"(p));
    return p;
}
__device__ __forceinline__ void mbar_init(uint32_t a, uint32_t cnt) {
    asm volatile("mbarrier.init.shared.b64 [%0], %1;" :: "r"(a), "r"(cnt) : "memory");
}
__device__ __forceinline__ void mbar_wait(uint32_t a, uint32_t parity) {
    asm volatile(
        "{\n\t.reg .pred P;\n\t"
        "LW_%=:\n\t"
        "mbarrier.try_wait.parity.acquire.cta.shared::cta.b64 P, [%0], %1, 0x989680;\n\t"
        "@P bra.uni LD_%=;\n\t"
        "bra.uni LW_%=;\n\t"
        "LD_%=:\n\t}"
        :: "r"(a), "r"(parity) : "memory");
}
__device__ __forceinline__ void fence_async_smem() {
    asm volatile("fence.proxy.async.shared::cta;" ::: "memory");
}
__device__ __forceinline__ void tmem_alloc(uint32_t smem_dst, uint32_t ncols) {
    asm volatile("tcgen05.alloc.cta_group::1.sync.aligned.shared::cta.b32 [%0], %1;"
                 :: "r"(smem_dst), "r"(ncols) : "memory");
}
__device__ __forceinline__ void tmem_relinquish() {
    asm volatile("tcgen05.relinquish_alloc_permit.cta_group::1.sync.aligned;");
}
__device__ __forceinline__ void tmem_dealloc(uint32_t tmem, uint32_t ncols) {
    asm volatile("tcgen05.dealloc.cta_group::1.sync.aligned.b32 %0, %1;" :: "r"(tmem), "r"(ncols));
}
__device__ __forceinline__ void mma_commit(uint32_t mbar) {
    asm volatile("tcgen05.commit.cta_group::1.mbarrier::arrive::one.shared::cluster.b64 [%0];"
                 :: "r"(mbar) : "memory");
}
__device__ __forceinline__ void fence_tc_after() {
    asm volatile("tcgen05.fence::after_thread_sync;" ::: "memory");
}
__device__ __forceinline__ void fence_tc_before() {
    asm volatile("tcgen05.fence::before_thread_sync;" ::: "memory");
}
__device__ __forceinline__ void mma_f16_ss(uint32_t d, uint64_t a, uint64_t b,
                                           uint32_t idesc, bool acc) {
    uint32_t e = acc ? 1u : 0u;
    asm volatile(
        "{\n\t.reg .pred p;\n\t"
        "setp.ne.u32 p, %5, 0;\n\t"
        "tcgen05.mma.cta_group::1.kind::f16 [%0], %1, %2, %3, {%4, %4, %4, %4}, p;\n\t}"
        :: "r"(d), "l"(a), "l"(b), "r"(idesc), "r"(0u), "r"(e) : "memory");
}
__device__ __forceinline__ void ldtm_x32(uint32_t* r, uint32_t tmem) {
    asm volatile(
        "tcgen05.ld.sync.aligned.32x32b.x32.b32 "
        "{%0,%1,%2,%3,%4,%5,%6,%7,%8,%9,%10,%11,%12,%13,%14,%15,"
        "%16,%17,%18,%19,%20,%21,%22,%23,%24,%25,%26,%27,%28,%29,%30,%31}, [%32];"
        : "=r"(r[0]), "=r"(r[1]), "=r"(r[2]), "=r"(r[3]), "=r"(r[4]), "=r"(r[5]),
          "=r"(r[6]), "=r"(r[7]), "=r"(r[8]), "=r"(r[9]), "=r"(r[10]), "=r"(r[11]),
          "=r"(r[12]), "=r"(r[13]), "=r"(r[14]), "=r"(r[15]), "=r"(r[16]), "=r"(r[17]),
          "=r"(r[18]), "=r"(r[19]), "=r"(r[20]), "=r"(r[21]), "=r"(r[22]), "=r"(r[23]),
          "=r"(r[24]), "=r"(r[25]), "=r"(r[26]), "=r"(r[27]), "=r"(r[28]), "=r"(r[29]),
          "=r"(r[30]), "=r"(r[31])
        : "r"(tmem));
}
__device__ __forceinline__ void tmem_wait_ld() {
    asm volatile("tcgen05.wait::ld.sync.aligned;" ::: "memory");
}
__device__ __forceinline__ uint64_t make_desc(uint32_t addr) {
    return ((uint64_t)2 << 61) | ((uint64_t)1 << 46) | ((uint64_t)64 << 32) |
           ((uint64_t)1 << 16) | (uint64_t)((addr >> 4) & 0x3FFF);
}

__device__ __forceinline__ void load_tile(const __nv_bfloat16* __restrict__ src,
                                          int row0, int kk, char* dst,
                                          int nrows, int tid) {
    int total = nrows * 8;
    for (int i = tid; i < total; i += THREADS) {
        int r = i >> 3, s = i & 7;
        uint4 v = *reinterpret_cast<const uint4*>(src + (size_t)(row0 + r) * K_DIM + kk + s * 8);
        uint32_t off = (uint32_t)(r << 7) + (uint32_t)(s << 4);
        off ^= (off >> 3) & 0x70;
        *reinterpret_cast<uint4*>(dst + off) = v;
    }
}

__global__ void __launch_bounds__(THREADS, 1)
qlinear_gemm_kernel(const float* __restrict__ scales,
                    const float* __restrict__ bias,
                    float* __restrict__ Out)
{
    extern __shared__ char smem[];
    const uint32_t sb = smem_u32(smem);
    const int tid = threadIdx.x;
    const int wid = tid >> 5;
    const int lid = tid & 31;

    const int n0 = blockIdx.x * BN;
    const int m0 = blockIdx.y * BM;

    if (wid == 0) {
        tmem_alloc(sb + OFF_TMEMPTR, BN);
        tmem_relinquish();
    }
    if (tid == 0) {
        mbar_init(sb + OFF_MBAR + 0, 1);
        mbar_init(sb + OFF_MBAR + 8, 1);
    }
    __syncthreads();

    uint32_t tmem;
    asm volatile("ld.shared.b32 %0, [%1];" : "=r"(tmem) : "r"(sb + OFF_TMEMPTR));

    {
        char* st = smem + OFF_BUF;
        load_tile(g_xh, m0, 0, st + AH_OFF, BM, tid);
        load_tile(g_xl, m0, 0, st + AL_OFF, BM, tid);
        load_tile(g_wb, n0, 0, st + BB_OFF, BN, tid);
        fence_async_smem();
    }
    __syncthreads();

    for (int c = 0; c < NCHUNK; c++) {
        const int bsel = c & 1;
        const uint32_t stage = sb + OFF_BUF + bsel * STAGE_BYTES;

        if (wid == 0) {
            fence_tc_after();
            uint64_t ah = make_desc(stage + AH_OFF);
            uint64_t al = make_desc(stage + AL_OFF);
            uint64_t bd = make_desc(stage + BB_OFF);
            if (elect_one()) {
                #pragma unroll
                for (int ks = 0; ks < 4; ks++)
                    mma_f16_ss(tmem, ah + ks * 2, bd + ks * 2, MMA_IDESC, (c > 0) || (ks > 0));
                #pragma unroll
                for (int ks = 0; ks < 4; ks++)
                    mma_f16_ss(tmem, al + ks * 2, bd + ks * 2, MMA_IDESC, true);
                mma_commit(sb + OFF_MBAR + bsel * 8);
            }
        }

        if (c >= 1)
            mbar_wait(sb + OFF_MBAR + (1 - bsel) * 8, ((c - 1) >> 1) & 1);

        if (c + 1 < NCHUNK) {
            char* st = smem + OFF_BUF + (1 - bsel) * STAGE_BYTES;
            int kk = (c + 1) * BK;
            load_tile(g_xh, m0, kk, st + AH_OFF, BM, tid);
            load_tile(g_xl, m0, kk, st + AL_OFF, BM, tid);
            load_tile(g_wb, n0, kk, st + BB_OFF, BN, tid);
            fence_async_smem();
        }
        __syncthreads();
    }

    mbar_wait(sb + OFF_MBAR + ((NCHUNK - 1) & 1) * 8, ((NCHUNK - 1) >> 1) & 1);
    fence_tc_after();

    if (wid < 4) {
        float* tp = reinterpret_cast<float*>(smem + OFF_BUF) + wid * (32 * 33);
        #pragma unroll 1
        for (int cb = 0; cb < BN / 32; cb++) {
            uint32_t r[32];
            ldtm_x32(r, tmem + cb * 32);
            tmem_wait_ld();
            #pragma unroll
            for (int j = 0; j < 32; j++)
                tp[lid * 33 + j] = __uint_as_float(r[j]);
            __syncwarp();
            int n = n0 + cb * 32 + lid;
            float s = scales[n];
            float b = bias[n];
            #pragma unroll 4
            for (int rr = 0; rr < 32; rr++) {
                float v = tp[rr * 33 + lid];
                Out[(size_t)(m0 + wid * 32 + rr) * N_DIM + n] = v * s + b;
            }
            __syncwarp();
        }
        fence_tc_before();
    }

    __syncthreads();
    if (wid == 0)
        tmem_dealloc(tmem, BN);
}

#else
// ================= wmma / HMMA fallback (plain sm_103 pass) =================

using namespace nvcuda;

__global__ void __launch_bounds__(THREADS, 1)
qlinear_gemm_kernel(const float* __restrict__ scales,
                    const float* __restrict__ bias,
                    float* __restrict__ Out)
{
    extern __shared__ char smem[];
    const int tid = threadIdx.x;
    const int wid = tid >> 5;
    const int lid = tid & 31;

    const int n0 = blockIdx.x * BN;
    const int m0 = blockIdx.y * BM;

    // warp layout: 2 (M) x 4 (N); warp tile 64x64
    const int wm = wid & 1;
    const int wn = wid >> 1;

    __nv_bfloat16* Ah = reinterpret_cast<__nv_bfloat16*>(smem + OFF_BUF + AH_OFF);
    __nv_bfloat16* Al = reinterpret_cast<__nv_bfloat16*>(smem + OFF_BUF + AL_OFF);
    __nv_bfloat16* Bs = reinterpret_cast<__nv_bfloat16*>(smem + OFF_BUF + BB_OFF);

    wmma::fragment<wmma::accumulator, 16, 16, 16, float> acc[4][4];
    #pragma unroll
    for (int mi = 0; mi < 4; mi++)
        #pragma unroll
        for (int ni = 0; ni < 4; ni++)
            wmma::fill_fragment(acc[mi][ni], 0.0f);

    for (int c = 0; c < NCHUNK; c++) {
        const int kk = c * BK;
        // cooperative loads, 16B segments, row pitch 64 bf16 (128B)
        #pragma unroll
        for (int it = 0; it < 4; it++) {
            int i = tid + it * THREADS;          // 1024 segs for A (128 rows x 8)
            int r = i >> 3, s = i & 7;
            *reinterpret_cast<uint4*>(Ah + r * 64 + s * 8) =
                *reinterpret_cast<const uint4*>(g_xh + (size_t)(m0 + r) * K_DIM + kk + s * 8);
            *reinterpret_cast<uint4*>(Al + r * 64 + s * 8) =
                *reinterpret_cast<const uint4*>(g_xl + (size_t)(m0 + r) * K_DIM + kk + s * 8);
        }
        #pragma unroll
        for (int it = 0; it < 8; it++) {
            int i = tid + it * THREADS;          // 2048 segs for B (256 rows x 8)
            int r = i >> 3, s = i & 7;
            *reinterpret_cast<uint4*>(Bs + r * 64 + s * 8) =
                *reinterpret_cast<const uint4*>(g_wb + (size_t)(n0 + r) * K_DIM + kk + s * 8);
        }
        __syncthreads();

        #pragma unroll
        for (int ks = 0; ks < 4; ks++) {
            wmma::fragment<wmma::matrix_b, 16, 16, 16, __nv_bfloat16, wmma::col_major> bf[4];
            #pragma unroll
            for (int ni = 0; ni < 4; ni++)
                wmma::load_matrix_sync(bf[ni], Bs + (wn * 64 + ni * 16) * 64 + ks * 16, 64);

            wmma::fragment<wmma::matrix_a, 16, 16, 16, __nv_bfloat16, wmma::row_major> af[4];
            #pragma unroll
            for (int mi = 0; mi < 4; mi++)
                wmma::load_matrix_sync(af[mi], Ah + (wm * 64 + mi * 16) * 64 + ks * 16, 64);
            #pragma unroll
            for (int mi = 0; mi < 4; mi++)
                #pragma unroll
                for (int ni = 0; ni < 4; ni++)
                    wmma::mma_sync(acc[mi][ni], af[mi], bf[ni], acc[mi][ni]);

            #pragma unroll
            for (int mi = 0; mi < 4; mi++)
                wmma::load_matrix_sync(af[mi], Al + (wm * 64 + mi * 16) * 64 + ks * 16, 64);
            #pragma unroll
            for (int mi = 0; mi < 4; mi++)
                #pragma unroll
                for (int ni = 0; ni < 4; ni++)
                    wmma::mma_sync(acc[mi][ni], af[mi], bf[ni], acc[mi][ni]);
        }
        __syncthreads();
    }

    // epilogue: per-warp smem patch, scale+bias, coalesced-ish stores
    float* patch = reinterpret_cast<float*>(smem + OFF_BUF) + wid * (16 * 68);
    #pragma unroll 1
    for (int mi = 0; mi < 4; mi++) {
        #pragma unroll
        for (int ni = 0; ni < 4; ni++)
            wmma::store_matrix_sync(patch + ni * 16, acc[mi][ni], 68, wmma::mem_row_major);
        __syncwarp();
        int mbase = m0 + wm * 64 + mi * 16;
        int nbase = n0 + wn * 64;
        #pragma unroll 4
        for (int e = lid; e < 16 * 64; e += 32) {
            int r = e >> 6, cc = e & 63;
            int n = nbase + cc;
            Out[(size_t)(mbase + r) * N_DIM + n] = patch[r * 68 + cc] * scales[n] + bias[n];
        }
        __syncwarp();
    }
}

#endif

// ---------------- host ----------------
extern "C" void kernel_launch(void* const* d_in, const int* in_sizes, int n_in,
                              void* d_out, int out_size)
{
    const float* x      = (const float*)d_in[0];
    const int*   w      = (const int*)d_in[1];
    const float* scales = (const float*)d_in[2];
    const float* bias   = (const float*)d_in[3];
    float* out = (float*)d_out;

    cudaFuncSetAttribute(qlinear_gemm_kernel,
                         cudaFuncAttributeMaxDynamicSharedMemorySize, SMEM_TOTAL);

    {
        int n4 = T_DIM * K_DIM / 4;
        convert_x_kernel<<<(n4 + 255) / 256, 256>>>((const float4*)x, n4);
    }
    {
        int n4 = N_DIM * K_DIM / 4;
        convert_w_kernel<<<(n4 + 255) / 256, 256>>>((const int4*)w, n4);
    }

    dim3 grid(N_DIM / BN, T_DIM / BM);
    qlinear_gemm_kernel<<<grid, THREADS, SMEM_TOTAL>>>(scales, bias, out);
}